// round 12
// baseline (speedup 1.0000x reference)
#include <cuda_runtime.h>
#include <cstdint>

// Problem constants (fixed by the reference setup).
#define BATCH 16
#define SEQ   4096
#define DIM   256            // floats per frame
#define QUADS (DIM / 4)      // 64 float4 per frame

#define SUPER        256                         // s values per super-chunk
#define SUPERS_PER_BATCH (SEQ / SUPER)           // 16
#define NSUPER       (BATCH * SUPERS_PER_BATCH)  // 256
#define NCOPY_BLOCKS ((BATCH * SEQ) / 8)         // 8192 (8 warps/block, 1 warp/s)
#define ZF_FRAMES    64                          // frames per zero-fill block

// Scratch: per-super-chunk sums of durations (256 ints).
__device__ int g_super[NSUPER];    // [b][cs] = sum of dims[b, cs*256:(cs+1)*256)

// ---------------------------------------------------------------------------
// Kernel 1: super sums. One warp per 256-s super-chunk (256 warps, 8 blocks).
// ---------------------------------------------------------------------------
__global__ __launch_bounds__(1024) void super_kernel(
    const int* __restrict__ dims)   // [B, S]
{
    const int w    = blockIdx.x * 32 + (threadIdx.x >> 5);  // 0..255
    const int lane = threadIdx.x & 31;

    const int4* dp = reinterpret_cast<const int4*>(dims) + (size_t)w * 64;
    const int4 a = __ldg(dp + lane);
    const int4 b = __ldg(dp + lane + 32);
    int v = a.x + a.y + a.z + a.w + b.x + b.y + b.z + b.w;
    v = __reduce_add_sync(0xFFFFFFFFu, v);
    if (lane == 0) g_super[w] = v;
}

// Sum of the first cnt elements of q (cnt clamped to [0,4] by the selects).
__device__ __forceinline__ int masked4(const int4 q, int cnt) {
    int s = 0;
    s += (cnt > 0) ? q.x : 0;
    s += (cnt > 1) ? q.y : 0;
    s += (cnt > 2) ? q.z : 0;
    s += (cnt > 3) ? q.w : 0;
    return s;
}

// ---------------------------------------------------------------------------
// Kernel 2: expand. No shared memory, no __syncthreads, no serial scan —
// every warp fully independent, prefix via ONE parallel masked reduce:
//   lanes 0..15 carry predecessor super sums (< cs);
//   every lane carries an element-masked sum of the current super's raw dims
//   (64 int4 total, 2 per lane, include elements with position < s mod 256).
// d = dims[s] is a single broadcast load. All prefix loads are L2-hit and
// overlap the warp's own 1KB x-row prefetch.
// ---------------------------------------------------------------------------
__global__ __launch_bounds__(256) void expand_kernel(
    const float* __restrict__ x,     // [B, S, D]
    const int*   __restrict__ dims,  // [B, S]
    float* __restrict__ out,         // [B, T, D]
    int T, int zb_per_batch)
{
    const int warp = threadIdx.x >> 5;
    const int lane = threadIdx.x & 31;

    if (blockIdx.x < NCOPY_BLOCKS) {
        // ================= copy role =================
        const int gw  = blockIdx.x * 8 + warp;       // 0 .. B*SEQ-1 (one warp per s)
        const int b   = gw >> 12;                    // SEQ = 4096
        const int sl  = gw & (SEQ - 1);              // s within batch
        const int cs  = sl >> 8;                     // super index, 0..15
        const int off = sl & (SUPER - 1);            // position within super

        // --- issue all prologue loads up front (latencies overlap) ---
        const int4* sp = reinterpret_cast<const int4*>(dims)
                       + ((size_t)(b << 4) + cs) * 64;       // current super's dims
        const int4 q0 = __ldg(sp + lane);
        const int4 q1 = __ldg(sp + lane + 32);
        int p = (lane < 16 && lane < cs) ? __ldg(g_super + (b << 4) + lane) : 0;
        const int d_own = __ldg(dims + ((size_t)b << 12) + sl);   // broadcast

        // --- prefetch this warp's 1KB source row (2 independent LDG.128) ---
        const float4* __restrict__ src =
            reinterpret_cast<const float4*>(x) + (size_t)gw * QUADS;
        const float4 v0 = __ldg(src + lane);
        const float4 v1 = __ldg(src + lane + 32);

        // --- start = supers + element-masked within-super sum ---
        p += masked4(q0, off - 4 * lane);
        p += masked4(q1, off - 4 * (lane + 32));
        const int start = __reduce_add_sync(0xFFFFFFFFu, p);

        if (d_own == 0) return;

        float4* __restrict__ o = reinterpret_cast<float4*>(out)
                               + ((size_t)b * T + start) * QUADS;
        for (int k = 0; k < d_own; k++) {
            __stcs(o + lane,      v0);
            __stcs(o + lane + 32, v1);
            o += QUADS;
        }
        return;
    }

    // ================= zero-fill role (warp-local total, no sync) =================
    {
        const int zb = blockIdx.x - NCOPY_BLOCKS;
        const int b  = zb / zb_per_batch;
        const int j  = zb - b * zb_per_batch;

        // total_b = sum of this batch's 16 super sums.
        int p = (lane < SUPERS_PER_BATCH) ? __ldg(g_super + (b << 4) + lane) : 0;
        const int total = __reduce_add_sync(0xFFFFFFFFu, p);

        const int base_frame = j * ZF_FRAMES;
        if (base_frame + ZF_FRAMES <= total) return;   // fully covered by copies

        const int base = base_frame * QUADS;           // float4 index within batch
        int end = (base_frame + ZF_FRAMES) * QUADS;
        const int tq = T * QUADS;
        if (end > tq) end = tq;
        const int lo = total * QUADS;                  // first padding float4

        float4* __restrict__ ob = reinterpret_cast<float4*>(out) + (size_t)b * tq;
        const float4 z = make_float4(0.f, 0.f, 0.f, 0.f);
        for (int e = base + threadIdx.x; e < end; e += 256)
            if (e >= lo) __stcs(ob + e, z);
    }
}

extern "C" void kernel_launch(void* const* d_in, const int* in_sizes, int n_in,
                              void* d_out, int out_size)
{
    const float* x    = (const float*)d_in[0];   // [B, S, D] float32
    const int*   dims = (const int*)d_in[1];     // [B, S, 1] int32
    float*       out  = (float*)d_out;           // [B, T, D] float32

    const int T = out_size / (BATCH * DIM);
    const int zb_per_batch = (T + ZF_FRAMES - 1) / ZF_FRAMES;

    super_kernel<<<NSUPER / 32, 1024>>>(dims);

    const int grid = NCOPY_BLOCKS + BATCH * zb_per_batch;
    expand_kernel<<<grid, 256>>>(x, dims, out, T, zb_per_batch);
}

// round 13
// speedup vs baseline: 1.0012x; 1.0012x over previous
#include <cuda_runtime.h>
#include <cstdint>

// Problem constants (fixed by the reference setup).
#define BATCH 16
#define SEQ   4096
#define DIM   256            // floats per frame
#define QUADS (DIM / 4)      // 64 float4 per frame

#define CHUNK        16                          // s values per level-1 chunk
#define CHUNKS_PER_BATCH (SEQ / CHUNK)           // 256
#define NCHUNKS      (BATCH * CHUNKS_PER_BATCH)  // 4096
#define SUPER        256                         // s values per level-2 super-chunk
#define SUPERS_PER_BATCH (SEQ / SUPER)           // 16
#define NSUPER       (BATCH * SUPERS_PER_BATCH)  // 256
#define NCOPY_BLOCKS ((BATCH * SEQ) / 8)         // 8192 (8 warps/block, 1 warp/s)
#define ZF_FRAMES    64                          // frames per zero-fill block

// Scratch: two-level partial sums of durations.
__device__ int g_part [NCHUNKS];   // [b][c]  sum of 16 durations
__device__ int g_super[NSUPER];    // [b][cs] sum of 256 durations

// ---------------------------------------------------------------------------
// Kernel 1: partials, both levels, each computed directly from dims
// (no inter-level dependency). One warp per chunk / super-chunk.
// ---------------------------------------------------------------------------
__global__ __launch_bounds__(1024) void partial_kernel(
    const int* __restrict__ dims)   // [B, S]
{
    const int w    = blockIdx.x * 32 + (threadIdx.x >> 5);
    const int lane = threadIdx.x & 31;

    if (w < NCHUNKS) {
        // level 1: sum of 16 durations
        int v = (lane < CHUNK) ? __ldg(dims + (size_t)w * CHUNK + lane) : 0;
        v = __reduce_add_sync(0xFFFFFFFFu, v);
        if (lane == 0) g_part[w] = v;
    } else {
        // level 2: sum of 256 durations (64 int4, 2 per lane)
        const int s = w - NCHUNKS;                 // 0..255 == b*16 + cs
        const int4* dp = reinterpret_cast<const int4*>(dims) + (size_t)s * 64;
        const int4 a = __ldg(dp + lane);
        const int4 b = __ldg(dp + lane + 32);
        int v = a.x + a.y + a.z + a.w + b.x + b.y + b.z + b.w;
        v = __reduce_add_sync(0xFFFFFFFFu, v);
        if (lane == 0) g_super[s] = v;
    }
}

// Sum of the first cnt elements of q (cnt outside [0,4] clamps via selects).
__device__ __forceinline__ int masked4(const int4 q, int cnt) {
    int s = 0;
    s += (cnt > 0) ? q.x : 0;
    s += (cnt > 1) ? q.y : 0;
    s += (cnt > 2) ? q.z : 0;
    s += (cnt > 3) ? q.w : 0;
    return s;
}

// ---------------------------------------------------------------------------
// Kernel 2: expand. No shared memory, no __syncthreads, no serial scan —
// every warp fully independent; start = ONE parallel masked reduce:
//   lanes 0..15  : predecessor super sums (< cs)
//   lanes 16..31 : predecessor level-1 sums within the current super (< cm)
//   lanes 0..3   : + element-masked sum of the current 16-duration chunk
//                  (4 int4 = 64B, L1-hot)
// d = dims[s] is a single broadcast load. All prologue loads overlap the
// warp's own 1KB x-row prefetch.
// ---------------------------------------------------------------------------
__global__ __launch_bounds__(256) void expand_kernel(
    const float* __restrict__ x,     // [B, S, D]
    const int*   __restrict__ dims,  // [B, S]
    float* __restrict__ out,         // [B, T, D]
    int T, int zb_per_batch)
{
    const int warp = threadIdx.x >> 5;
    const int lane = threadIdx.x & 31;

    if (blockIdx.x < NCOPY_BLOCKS) {
        // ================= copy role =================
        const int gw = blockIdx.x * 8 + warp;        // 0 .. B*SEQ-1 (one warp per s)
        const int b  = gw >> 12;                     // SEQ = 4096
        const int sl = gw & (SEQ - 1);               // s within batch
        const int c  = sl >> 4;                      // chunk index, 0..255
        const int cs = c >> 4;                       // super index, 0..15
        const int cm = c & 15;                       // chunk within super
        const int r  = sl & (CHUNK - 1);             // rank within chunk

        // --- issue all prologue loads up front (latencies overlap) ---
        int p = 0;
        if (lane < 16) {
            if (lane < cs) p = __ldg(g_super + (b << 4) + lane);
        } else {
            const int j = lane - 16;
            if (j < cm)  p = __ldg(g_part + (b << 8) + (cs << 4) + j);
        }
        int4 cq = make_int4(0, 0, 0, 0);
        if (lane < 4)
            cq = __ldg(reinterpret_cast<const int4*>(dims)
                       + ((size_t)b << 10) + (c << 2) + lane);
        const int d_own = __ldg(dims + ((size_t)b << 12) + sl);   // broadcast

        // --- prefetch this warp's 1KB source row (2 independent LDG.128) ---
        const float4* __restrict__ src =
            reinterpret_cast<const float4*>(x) + (size_t)gw * QUADS;
        const float4 v0 = __ldg(src + lane);
        const float4 v1 = __ldg(src + lane + 32);

        // --- start = supers + parts + element-masked chunk sum, ONE reduce ---
        p += masked4(cq, r - 4 * lane);              // only lanes 0..3 contribute
        const int start = __reduce_add_sync(0xFFFFFFFFu, p);

        if (d_own == 0) return;

        float4* __restrict__ o = reinterpret_cast<float4*>(out)
                               + ((size_t)b * T + start) * QUADS;
        for (int k = 0; k < d_own; k++) {
            __stcs(o + lane,      v0);
            __stcs(o + lane + 32, v1);
            o += QUADS;
        }
        return;
    }

    // ================= zero-fill role (warp-local total, no sync) =================
    {
        const int zb = blockIdx.x - NCOPY_BLOCKS;
        const int b  = zb / zb_per_batch;
        const int j  = zb - b * zb_per_batch;

        // total_b = sum of this batch's 16 super sums.
        int p = (lane < SUPERS_PER_BATCH) ? __ldg(g_super + (b << 4) + lane) : 0;
        const int total = __reduce_add_sync(0xFFFFFFFFu, p);

        const int base_frame = j * ZF_FRAMES;
        if (base_frame + ZF_FRAMES <= total) return;   // fully covered by copies

        const int base = base_frame * QUADS;           // float4 index within batch
        int end = (base_frame + ZF_FRAMES) * QUADS;
        const int tq = T * QUADS;
        if (end > tq) end = tq;
        const int lo = total * QUADS;                  // first padding float4

        float4* __restrict__ ob = reinterpret_cast<float4*>(out) + (size_t)b * tq;
        const float4 z = make_float4(0.f, 0.f, 0.f, 0.f);
        for (int e = base + threadIdx.x; e < end; e += 256)
            if (e >= lo) __stcs(ob + e, z);
    }
}

extern "C" void kernel_launch(void* const* d_in, const int* in_sizes, int n_in,
                              void* d_out, int out_size)
{
    const float* x    = (const float*)d_in[0];   // [B, S, D] float32
    const int*   dims = (const int*)d_in[1];     // [B, S, 1] int32
    float*       out  = (float*)d_out;           // [B, T, D] float32

    const int T = out_size / (BATCH * DIM);
    const int zb_per_batch = (T + ZF_FRAMES - 1) / ZF_FRAMES;

    partial_kernel<<<(NCHUNKS + NSUPER) / 32, 1024>>>(dims);

    const int grid = NCOPY_BLOCKS + BATCH * zb_per_batch;
    expand_kernel<<<grid, 256>>>(x, dims, out, T, zb_per_batch);
}